// round 12
// baseline (speedup 1.0000x reference)
#include <cuda_runtime.h>
#include <cstdint>

constexpr int NL  = 6;
constexpr int NH  = 16;
constexpr int DM  = 1024;
constexpr int DH  = 64;
constexpr int DFF = 4096;
constexpr int NV  = 32000;
constexpr int NB  = 2;
constexpr int NS  = 1024;
constexpr int NT  = NB * NS;

__device__ float g_x  [NT * DM];                 // fp32 (residual path)
__device__ float g_xr [NT * DM];                 // tf32-rounded copy
__device__ float g_res[NT * DM];
__device__ float g_qkv[3 * NT * DM];             // rounded
__device__ float g_o  [NT * DM];                 // rounded
__device__ float g_ffn[NT * DFF];                // rounded
__device__ float g_vt [NB * NH * DH * NS];       // rounded V^T per head
__device__ float g_bt [(long)NV * DM];           // rounded transposed weights

__device__ __forceinline__ float f2tff(float f) {
    unsigned u;
    asm("cvt.rna.tf32.f32 %0, %1;" : "=r"(u) : "f"(f));
    return __uint_as_float(u);
}
__device__ __forceinline__ void mma8(float* c, const uint4& a, unsigned b0, unsigned b1) {
    asm volatile(
        "mma.sync.aligned.m16n8k8.row.col.f32.tf32.tf32.f32 "
        "{%0,%1,%2,%3}, {%4,%5,%6,%7}, {%8,%9}, {%0,%1,%2,%3};"
        : "+f"(c[0]), "+f"(c[1]), "+f"(c[2]), "+f"(c[3])
        : "r"(a.x), "r"(a.y), "r"(a.z), "r"(a.w), "r"(b0), "r"(b1));
}
__device__ __forceinline__ uint4 ldm4(unsigned addr) {
    uint4 r;
    asm volatile("ldmatrix.sync.aligned.m8n8.x4.shared.b16 {%0,%1,%2,%3}, [%4];"
                 : "=r"(r.x), "=r"(r.y), "=r"(r.z), "=r"(r.w) : "r"(addr));
    return r;
}
__device__ __forceinline__ void cp16(unsigned sm, const void* g) {
    asm volatile("cp.async.ca.shared.global [%0], [%1], 16;" :: "r"(sm), "l"(g));
}
#define CP_COMMIT asm volatile("cp.async.commit_group;" ::: "memory")
#define CP_WAIT1  asm volatile("cp.async.wait_group 1;" ::: "memory")
#define CP_WAIT0  asm volatile("cp.async.wait_group 0;" ::: "memory")

__device__ __forceinline__ unsigned smu32(const void* p) {
    return (unsigned)__cvta_generic_to_shared(p);
}

// ---------------------------------------------------------------------------
// Vectorized transpose + tf32 round: in (per z: [K][N], ld ldin) -> out[(z*N+n)*K+k]
// ---------------------------------------------------------------------------
__global__ void __launch_bounds__(256)
tr32v(const float* __restrict__ in, float* __restrict__ out,
      int K, int N, int ldin, int zdiv, long sZb, long sZh)
{
    __shared__ float t[32][33];
    const int z = blockIdx.z, zb = z / zdiv, zh = z % zdiv;
    in += zb * sZb + zh * sZh;
    const int k0 = blockIdx.x * 32, n0 = blockIdx.y * 32;
    const int r = threadIdx.x >> 3, c = (threadIdx.x & 7) * 4;

    const float4 v = *(const float4*)&in[(long)(k0 + r) * ldin + n0 + c];
    t[r][c] = v.x; t[r][c + 1] = v.y; t[r][c + 2] = v.z; t[r][c + 3] = v.w;
    __syncthreads();

    float4 o4;
    o4.x = f2tff(t[c + 0][r]);
    o4.y = f2tff(t[c + 1][r]);
    o4.z = f2tff(t[c + 2][r]);
    o4.w = f2tff(t[c + 3][r]);
    *(float4*)&out[((long)z * N + n0 + r) * K + k0 + c] = o4;
}

// ---------------------------------------------------------------------------
// tf32 TC GEMM: BM=64, BN=128, BK=16, 128 threads (4 warps: 2M x 2N,
// warp tile 32x64). 3-stage cp.async pipeline, ldmatrix both operands.
// A [m][k] pre-rounded fp32, Bt [n][k] pre-rounded fp32.
// flags: 1=bias, 2=residual, 4=relu, 16=round output
// ---------------------------------------------------------------------------
constexpr int ST   = 20;
constexpr int ABUF = 64 * ST;                   // 1280 words
constexpr int BBUF = 128 * ST;                  // 2560 words
constexpr int GSMEM = 3 * (ABUF + BBUF) * 4;    // 46080 bytes -> 4 CTAs/SM

__global__ void __launch_bounds__(128, 4)
gemm_tc(const float* __restrict__ A, const float* __restrict__ Bt,
        const float* __restrict__ bias, const float* __restrict__ Res,
        float* __restrict__ C, int K, int lda, int ldb, int ldc, int zdiv,
        long sAb, long sAh, long sBb, long sBh, long sCb, long sCh,
        int flags)
{
    extern __shared__ unsigned smem[];
    unsigned* Asm = smem;
    unsigned* Bsm = smem + 3 * ABUF;

    const int zb = blockIdx.z / zdiv, zh = blockIdx.z % zdiv;
    A  += zb * sAb + zh * sAh;
    Bt += zb * sBb + zh * sBh;
    const long coff = (long)zb * sCb + (long)zh * sCh;

    const int m0 = blockIdx.x * 64;
    const int n0 = blockIdx.y * 128;
    const int tid = threadIdx.x;

    // A fill: 64 rows x 16 floats, 128 threads -> 8 floats (2 cp16) each
    const int ar = tid >> 1, aw = (tid & 1) * 8;
    const float* Ag = A + (long)(m0 + ar) * lda + aw;
    const unsigned aDst = smu32(&Asm[ar * ST + aw]);
    // B fill: 128 rows x 16 floats, 1 thread per row -> 16 floats (4 cp16)
    const float* Bg = Bt + (long)(n0 + tid) * ldb;
    const unsigned bDst = smu32(&Bsm[tid * ST]);

    const int nit = K / 16;
    auto fill = [&](int s) {
        const int st = s % 3;
        const unsigned ao = aDst + st * (ABUF * 4);
        const float* ag = Ag + s * 16;
        cp16(ao, ag); cp16(ao + 16, ag + 4);
        const unsigned bo = bDst + st * (BBUF * 4);
        const float* bg = Bg + s * 16;
        #pragma unroll
        for (int j = 0; j < 4; j++) cp16(bo + j * 16, bg + j * 4);
    };

    const int lane = tid & 31, wid = tid >> 5;
    const int wm = wid & 1, wn = wid >> 1;
    const int grp = lane >> 2, qd = lane & 3;

    const unsigned aAddr = smu32(&Asm[(wm * 32 + (lane & 15)) * ST + ((lane & 16) >> 2)]);
    const unsigned bAddr = smu32(&Bsm[(wn * 64 + (lane & 15)) * ST + ((lane & 16) >> 2)]);

    float acc[2][8][4];
    #pragma unroll
    for (int i = 0; i < 2; i++)
        #pragma unroll
        for (int j = 0; j < 8; j++)
            #pragma unroll
            for (int l = 0; l < 4; l++) acc[i][j][l] = 0.f;

    fill(0); CP_COMMIT;
    if (nit > 1) fill(1);
    CP_COMMIT;

    for (int it = 0; it < nit; it++) {
        CP_WAIT1;
        __syncthreads();
        if (it + 2 < nit) fill(it + 2);
        CP_COMMIT;

        const int st = it % 3;
        const unsigned aC = aAddr + st * (ABUF * 4);
        const unsigned bC = bAddr + st * (BBUF * 4);
        #pragma unroll
        for (int ks = 0; ks < 2; ks++) {
            const uint4 a0 = ldm4(aC + (ks * 8) * 4);
            const uint4 a1 = ldm4(aC + (16 * ST + ks * 8) * 4);
            #pragma unroll
            for (int p = 0; p < 4; p++) {
                const uint4 bv = ldm4(bC + (p * 16 * ST + ks * 8) * 4);
                mma8(acc[0][2 * p],     a0, bv.x, bv.z);
                mma8(acc[0][2 * p + 1], a0, bv.y, bv.w);
                mma8(acc[1][2 * p],     a1, bv.x, bv.z);
                mma8(acc[1][2 * p + 1], a1, bv.y, bv.w);
            }
        }
    }

    const bool dob = flags & 1, dores = flags & 2, dorelu = flags & 4,
               dornd = flags & 16;
    #pragma unroll
    for (int mt = 0; mt < 2; mt++) {
        #pragma unroll
        for (int nt = 0; nt < 8; nt++) {
            const int r = m0 + wm * 32 + mt * 16 + grp;
            const int c = n0 + wn * 64 + nt * 8 + qd * 2;
            #pragma unroll
            for (int hf = 0; hf < 2; hf++) {
                const int rr = r + hf * 8;
                float v0 = acc[mt][nt][hf * 2 + 0];
                float v1 = acc[mt][nt][hf * 2 + 1];
                if (dob) { v0 += bias[c]; v1 += bias[c + 1]; }
                if (dores) {
                    const float* rp = Res + coff + (long)rr * ldc + c;
                    v0 += rp[0]; v1 += rp[1];
                }
                if (dorelu) { v0 = fmaxf(v0, 0.f); v1 = fmaxf(v1, 0.f); }
                if (dornd) { v0 = f2tff(v0); v1 = f2tff(v1); }
                *(float2*)(C + coff + (long)rr * ldc + c) = make_float2(v0, v1);
            }
        }
    }
}

// ---------------------------------------------------------------------------
// Flash attention: 128 q-rows per CTA, 64-wide j tiles, online softmax.
// ---------------------------------------------------------------------------
constexpr int FST = 68;
constexpr int FA_SMEM = (128 * FST + 64 * FST + 64 * FST + 128 * FST) * 4;

__global__ void __launch_bounds__(256, 2)
flash_attn(const float* __restrict__ q, const float* __restrict__ k,
           const float* __restrict__ vt, float* __restrict__ o)
{
    extern __shared__ float fsm[];
    float* Qs  = fsm;
    float* Ks  = Qs  + 128 * FST;
    float* Vts = Ks  + 64 * FST;
    float* Ps  = Vts + 64 * FST;

    const int z = blockIdx.y;
    const int b = z >> 4, h = z & 15;
    const int i0 = blockIdx.x * 128;
    const int tid = threadIdx.x, lane = tid & 31, w = tid >> 5;
    const int grp = lane >> 2, qd = lane & 3;

    {   // Q fill
        const int r = tid >> 1, cb = (tid & 1) * 32;
        const float* src = q + (long)(b * NS + i0 + r) * DM + h * DH + cb;
        unsigned dst = smu32(Qs + r * FST + cb);
        #pragma unroll
        for (int i = 0; i < 8; i++) cp16(dst + i * 16, src + i * 4);
        CP_COMMIT;
    }

    const int r0 = w * 16;
    const int gr = i0 + r0 + grp;
    const unsigned qAddr = smu32(Qs + (r0 + (lane & 15)) * FST + ((lane & 16) >> 2));
    const unsigned kAddr = smu32(Ks + (lane & 15) * FST + ((lane & 16) >> 2));
    const unsigned vAddr = smu32(Vts + (lane & 15) * FST + ((lane & 16) >> 2));
    const unsigned pAddr = smu32(Ps + (r0 + (lane & 15)) * FST + ((lane & 16) >> 2));

    float m0 = -1e30f, m1 = -1e30f, l0 = 0.f, l1 = 0.f;
    float oacc[8][4];
    #pragma unroll
    for (int i = 0; i < 8; i++)
        #pragma unroll
        for (int j = 0; j < 4; j++) oacc[i][j] = 0.f;

    const int ntiles = i0 / 64 + 2;

    for (int jt = 0; jt < ntiles; jt++) {
        const int j0 = jt * 64;
        __syncthreads();
        {
            const int jj = tid >> 2, cb = (tid & 3) * 4;
            const float* ks = k + (long)(b * NS + j0 + jj) * DM + h * DH + cb;
            unsigned kd = smu32(Ks + jj * FST + cb);
            #pragma unroll
            for (int i = 0; i < 4; i++) cp16(kd + i * 64, ks + i * 16);
            const float* vs = vt + ((long)z * DH + jj) * NS + j0 + cb;
            unsigned vd = smu32(Vts + jj * FST + cb);
            #pragma unroll
            for (int i = 0; i < 4; i++) cp16(vd + i * 64, vs + i * 16);
            CP_COMMIT;
        }
        CP_WAIT0;
        __syncthreads();

        if (j0 <= i0 + r0 + 15) {
            float sacc[8][4];
            #pragma unroll
            for (int i = 0; i < 8; i++)
                #pragma unroll
                for (int j = 0; j < 4; j++) sacc[i][j] = 0.f;

            #pragma unroll
            for (int ks = 0; ks < 8; ks++) {
                const uint4 af = ldm4(qAddr + (ks * 8) * 4);
                #pragma unroll
                for (int p = 0; p < 4; p++) {
                    const uint4 bv = ldm4(kAddr + (p * 16 * FST + ks * 8) * 4);
                    mma8(sacc[2 * p],     af, bv.x, bv.z);
                    mma8(sacc[2 * p + 1], af, bv.y, bv.w);
                }
            }

            float mx0 = -1e30f, mx1 = -1e30f;
            #pragma unroll
            for (int nt = 0; nt < 8; nt++) {
                const int jc = j0 + nt * 8 + qd * 2;
                float v0 = sacc[nt][0] * 0.125f, v1 = sacc[nt][1] * 0.125f;
                float v2 = sacc[nt][2] * 0.125f, v3 = sacc[nt][3] * 0.125f;
                if (jc     > gr)     v0 = -1e30f;
                if (jc + 1 > gr)     v1 = -1e30f;
                if (jc     > gr + 8) v2 = -1e30f;
                if (jc + 1 > gr + 8) v3 = -1e30f;
                sacc[nt][0] = v0; sacc[nt][1] = v1; sacc[nt][2] = v2; sacc[nt][3] = v3;
                mx0 = fmaxf(mx0, fmaxf(v0, v1));
                mx1 = fmaxf(mx1, fmaxf(v2, v3));
            }
            mx0 = fmaxf(mx0, __shfl_xor_sync(0xffffffffu, mx0, 1));
            mx0 = fmaxf(mx0, __shfl_xor_sync(0xffffffffu, mx0, 2));
            mx1 = fmaxf(mx1, __shfl_xor_sync(0xffffffffu, mx1, 1));
            mx1 = fmaxf(mx1, __shfl_xor_sync(0xffffffffu, mx1, 2));
            const float mn0 = fmaxf(m0, mx0), mn1 = fmaxf(m1, mx1);
            const float es0 = expf(m0 - mn0), es1 = expf(m1 - mn1);
            m0 = mn0; m1 = mn1;

            float rs0 = 0.f, rs1 = 0.f;
            const int lr = r0 + grp;
            #pragma unroll
            for (int nt = 0; nt < 8; nt++) {
                const float p0 = expf(sacc[nt][0] - mn0);
                const float p1 = expf(sacc[nt][1] - mn0);
                const float p2 = expf(sacc[nt][2] - mn1);
                const float p3 = expf(sacc[nt][3] - mn1);
                rs0 += p0 + p1; rs1 += p2 + p3;
                *(float2*)(Ps + lr * FST + nt * 8 + qd * 2) =
                    make_float2(f2tff(p0), f2tff(p1));
                *(float2*)(Ps + (lr + 8) * FST + nt * 8 + qd * 2) =
                    make_float2(f2tff(p2), f2tff(p3));
            }
            rs0 += __shfl_xor_sync(0xffffffffu, rs0, 1);
            rs0 += __shfl_xor_sync(0xffffffffu, rs0, 2);
            rs1 += __shfl_xor_sync(0xffffffffu, rs1, 1);
            rs1 += __shfl_xor_sync(0xffffffffu, rs1, 2);
            l0 = l0 * es0 + rs0;
            l1 = l1 * es1 + rs1;

            #pragma unroll
            for (int nt = 0; nt < 8; nt++) {
                oacc[nt][0] *= es0; oacc[nt][1] *= es0;
                oacc[nt][2] *= es1; oacc[nt][3] *= es1;
            }
            __syncwarp();

            #pragma unroll
            for (int ks = 0; ks < 8; ks++) {
                const uint4 pf = ldm4(pAddr + (ks * 8) * 4);
                #pragma unroll
                for (int p = 0; p < 4; p++) {
                    const uint4 bv = ldm4(vAddr + (p * 16 * FST + ks * 8) * 4);
                    mma8(oacc[2 * p],     pf, bv.x, bv.z);
                    mma8(oacc[2 * p + 1], pf, bv.y, bv.w);
                }
            }
        }
    }

    const float inv0 = 1.f / l0, inv1 = 1.f / l1;
    #pragma unroll
    for (int nt = 0; nt < 8; nt++) {
        const int c = h * DH + nt * 8 + qd * 2;
        *(float2*)(o + (long)(b * NS + gr) * DM + c) =
            make_float2(f2tff(oacc[nt][0] * inv0), f2tff(oacc[nt][1] * inv0));
        *(float2*)(o + (long)(b * NS + gr + 8) * DM + c) =
            make_float2(f2tff(oacc[nt][2] * inv1), f2tff(oacc[nt][3] * inv1));
    }
}

// ---------------------------------------------------------------------------
__global__ void __launch_bounds__(256)
ln_kernel(const float* __restrict__ in, const float* __restrict__ g,
          const float* __restrict__ b, float* __restrict__ out,
          float* __restrict__ outr)
{
    const float* p = in + (long)blockIdx.x * DM;
    float* po  = out  + (long)blockIdx.x * DM;
    float* por = outr + (long)blockIdx.x * DM;
    const int tid = threadIdx.x;
    __shared__ float red[256];
    float vals[4];
    float s = 0.f;
    #pragma unroll
    for (int i = 0; i < 4; i++) { vals[i] = p[tid + i * 256]; s += vals[i]; }
    red[tid] = s; __syncthreads();
    for (int st = 128; st > 0; st >>= 1) {
        if (tid < st) red[tid] += red[tid + st];
        __syncthreads();
    }
    const float mean = red[0] * (1.f / DM); __syncthreads();
    float sq = 0.f;
    #pragma unroll
    for (int i = 0; i < 4; i++) { float d = vals[i] - mean; sq += d * d; }
    red[tid] = sq; __syncthreads();
    for (int st = 128; st > 0; st >>= 1) {
        if (tid < st) red[tid] += red[tid + st];
        __syncthreads();
    }
    const float sd = sqrtf(red[0] / (DM - 1));
    const float inv = 1.f / (sd + 1e-6f);
    #pragma unroll
    for (int i = 0; i < 4; i++) {
        const int d = tid + i * 256;
        const float r = g[d] * (vals[i] - mean) * inv + b[d];
        po[d] = r;
        por[d] = f2tff(r);
    }
}

__global__ void __launch_bounds__(256)
embed_kernel(const int* __restrict__ tokens, const float* __restrict__ emb,
             float* __restrict__ x, float* __restrict__ xr)
{
    const int t = blockIdx.x;
    const int s = t & (NS - 1);
    const float* e = emb + (long)tokens[t] * DM;
    float* xo  = x  + (long)t * DM;
    float* xro = xr + (long)t * DM;
    const float nlog = -9.210340371976184f / (float)DM;
    for (int d = threadIdx.x; d < DM; d += 256) {
        const float freq = expf((float)(d & ~1) * nlog);
        const float ang = (float)s * freq;
        const float r = e[d] * 32.0f + ((d & 1) ? cosf(ang) : sinf(ang));
        xo[d] = r;
        xro[d] = f2tff(r);
    }
}

// ---------------------------------------------------------------------------
extern "C" void kernel_launch(void* const* d_in, const int* in_sizes, int n_in,
                              void* d_out, int out_size)
{
    const int*   tokens = (const int*)  d_in[0];
    const float* emb    = (const float*)d_in[1];
    const float* Wq     = (const float*)d_in[2];
    const float* Wk     = (const float*)d_in[3];
    const float* Wv     = (const float*)d_in[4];
    const float* Wo     = (const float*)d_in[5];
    const float* bo     = (const float*)d_in[6];
    const float* ln1g   = (const float*)d_in[7];
    const float* ln1b   = (const float*)d_in[8];
    const float* W1     = (const float*)d_in[9];
    const float* b1     = (const float*)d_in[10];
    const float* W2     = (const float*)d_in[11];
    const float* b2     = (const float*)d_in[12];
    const float* ln2g   = (const float*)d_in[13];
    const float* ln2b   = (const float*)d_in[14];
    const float* Wout   = (const float*)d_in[15];
    const float* bout   = (const float*)d_in[16];
    float* out = (float*)d_out;

    float *x, *xr, *res, *qkv, *o, *ffn, *vt, *bt;
    cudaGetSymbolAddress((void**)&x,   g_x);
    cudaGetSymbolAddress((void**)&xr,  g_xr);
    cudaGetSymbolAddress((void**)&res, g_res);
    cudaGetSymbolAddress((void**)&qkv, g_qkv);
    cudaGetSymbolAddress((void**)&o,   g_o);
    cudaGetSymbolAddress((void**)&ffn, g_ffn);
    cudaGetSymbolAddress((void**)&vt,  g_vt);
    cudaGetSymbolAddress((void**)&bt,  g_bt);

    cudaFuncSetAttribute(gemm_tc,    cudaFuncAttributeMaxDynamicSharedMemorySize, GSMEM);
    cudaFuncSetAttribute(flash_attn, cudaFuncAttributeMaxDynamicSharedMemorySize, FA_SMEM);
    // Max smem carveout so 4 gemm CTAs (184 KB) / 2 FA CTAs (205 KB) fit per SM.
    cudaFuncSetAttribute(gemm_tc,    cudaFuncAttributePreferredSharedMemoryCarveout, 100);
    cudaFuncSetAttribute(flash_attn, cudaFuncAttributePreferredSharedMemoryCarveout, 100);

    float* q = qkv;
    float* k = qkv + NT * DM;
    float* v = qkv + 2 * NT * DM;
    const long HW = (long)NH * DM * DH;

    embed_kernel<<<NT, 256>>>(tokens, emb, x, xr);

    for (int l = 0; l < NL; l++) {
        // QKV weights -> bt[(h*64+n)*DM + k] (rounded), fused z=3 GEMM
        tr32v<<<dim3(DM / 32, DH / 32, NH), 256>>>(Wq + l * HW, bt,          DM, DH, DH, NH, 0, (long)DM * DH);
        tr32v<<<dim3(DM / 32, DH / 32, NH), 256>>>(Wk + l * HW, bt + HW,     DM, DH, DH, NH, 0, (long)DM * DH);
        tr32v<<<dim3(DM / 32, DH / 32, NH), 256>>>(Wv + l * HW, bt + 2 * HW, DM, DH, DH, NH, 0, (long)DM * DH);
        gemm_tc<<<dim3(NT / 64, DM / 128, 3), 128, GSMEM>>>(
            xr, bt, nullptr, nullptr, qkv, DM, DM, DM, DM, 3,
            0, 0, 0, HW, 0, (long)NT * DM, 16);

        // V^T per head (rounded)
        tr32v<<<dim3(NS / 32, DH / 32, NB * NH), 256>>>(
            v, vt, NS, DH, DM, NH, (long)NS * DM, DH);

        // flash attention -> o (rounded)
        flash_attn<<<dim3(NS / 128, NB * NH), 256, FA_SMEM>>>(q, k, vt, o);

        // O projection + bias + residual (fp32 out)
        tr32v<<<dim3(DM / 32, DM / 32, 1), 256>>>(Wo + (long)l * DM * DM, bt, DM, DM, DM, 1, 0, 0);
        gemm_tc<<<dim3(NT / 64, DM / 128), 128, GSMEM>>>(
            o, bt, bo + l * DM, x, res, DM, DM, DM, DM, 1,
            0, 0, 0, 0, 0, 0, 1 | 2);
        ln_kernel<<<NT, 256>>>(res, ln1g + l * DM, ln1b + l * DM, x, xr);

        // FFN
        tr32v<<<dim3(DM / 32, DFF / 32, 1), 256>>>(W1 + (long)l * DM * DFF, bt, DM, DFF, DFF, 1, 0, 0);
        gemm_tc<<<dim3(NT / 64, DFF / 128), 128, GSMEM>>>(
            xr, bt, b1 + l * DFF, nullptr, ffn, DM, DM, DM, DFF, 1,
            0, 0, 0, 0, 0, 0, 1 | 4 | 16);
        tr32v<<<dim3(DFF / 32, DM / 32, 1), 256>>>(W2 + (long)l * DFF * DM, bt, DFF, DM, DM, 1, 0, 0);
        gemm_tc<<<dim3(NT / 64, DM / 128), 128, GSMEM>>>(
            ffn, bt, b2 + l * DM, x, res, DFF, DFF, DFF, DM, 1,
            0, 0, 0, 0, 0, 0, 1 | 2);
        ln_kernel<<<NT, 256>>>(res, ln2g + l * DM, ln2b + l * DM, x, xr);
    }

    // final vocab projection
    tr32v<<<dim3(DM / 32, NV / 32, 1), 256>>>(Wout, bt, DM, NV, NV, 1, 0, 0);
    gemm_tc<<<dim3(NT / 64, NV / 128), 128, GSMEM>>>(
        xr, bt, bout, nullptr, out, DM, DM, DM, NV, 1,
        0, 0, 0, 0, 0, 0, 1);
}

// round 13
// speedup vs baseline: 2.8899x; 2.8899x over previous
#include <cuda_runtime.h>
#include <cuda_fp16.h>
#include <cstdint>

constexpr int NL  = 6;
constexpr int NH  = 16;
constexpr int DM  = 1024;
constexpr int DH  = 64;
constexpr int DFF = 4096;
constexpr int NV  = 32000;
constexpr int NB  = 2;
constexpr int NS  = 1024;
constexpr int NT  = NB * NS;

__device__ float  g_x  [NT * DM];                 // fp32 residual path
__device__ __half g_xh [NT * DM];                 // fp16 copy
__device__ float  g_res[NT * DM];
__device__ __half g_qkv[3 * NT * DM];             // fp16 q,k,v
__device__ __half g_o  [NT * DM];                 // fp16 attn out
__device__ __half g_ffn[NT * DFF];                // fp16
__device__ __half g_vt [NB * NH * DH * NS];       // fp16 V^T per head
__device__ __half g_bt [(long)NV * DM];           // fp16 transposed weights [n][k]

__device__ __forceinline__ void mma16(float* c, const uint4& a, unsigned b0, unsigned b1) {
    asm volatile(
        "mma.sync.aligned.m16n8k16.row.col.f32.f16.f16.f32 "
        "{%0,%1,%2,%3}, {%4,%5,%6,%7}, {%8,%9}, {%0,%1,%2,%3};"
        : "+f"(c[0]), "+f"(c[1]), "+f"(c[2]), "+f"(c[3])
        : "r"(a.x), "r"(a.y), "r"(a.z), "r"(a.w), "r"(b0), "r"(b1));
}
__device__ __forceinline__ uint4 ldm4(unsigned addr) {
    uint4 r;
    asm volatile("ldmatrix.sync.aligned.m8n8.x4.shared.b16 {%0,%1,%2,%3}, [%4];"
                 : "=r"(r.x), "=r"(r.y), "=r"(r.z), "=r"(r.w) : "r"(addr));
    return r;
}
__device__ __forceinline__ void cp16(unsigned sm, const void* g) {
    asm volatile("cp.async.ca.shared.global [%0], [%1], 16;" :: "r"(sm), "l"(g));
}
#define CP_COMMIT asm volatile("cp.async.commit_group;" ::: "memory")
#define CP_WAIT1  asm volatile("cp.async.wait_group 1;" ::: "memory")
#define CP_WAIT0  asm volatile("cp.async.wait_group 0;" ::: "memory")

__device__ __forceinline__ unsigned smu32(const void* p) {
    return (unsigned)__cvta_generic_to_shared(p);
}
__device__ __forceinline__ unsigned h2pack(float a, float b) {
    const __half2 h = __floats2half2_rn(a, b);
    return *(const unsigned*)&h;
}

// ---------------------------------------------------------------------------
// Transpose fp32 -> fp16: in (per z: [K][N], ld ldin) -> out[(z*N+n)*K + k]
// ---------------------------------------------------------------------------
__global__ void __launch_bounds__(256)
tr16(const float* __restrict__ in, __half* __restrict__ out,
     int K, int N, int ldin, int zdiv, long sZb, long sZh)
{
    __shared__ float t[32][33];
    const int z = blockIdx.z, zb = z / zdiv, zh = z % zdiv;
    in += zb * sZb + zh * sZh;
    const int k0 = blockIdx.x * 32, n0 = blockIdx.y * 32;
    const int r = threadIdx.x >> 3, c = (threadIdx.x & 7) * 4;

    const float4 v = *(const float4*)&in[(long)(k0 + r) * ldin + n0 + c];
    t[r][c] = v.x; t[r][c + 1] = v.y; t[r][c + 2] = v.z; t[r][c + 3] = v.w;
    __syncthreads();

    uint2 o2;
    o2.x = h2pack(t[c + 0][r], t[c + 1][r]);
    o2.y = h2pack(t[c + 2][r], t[c + 3][r]);
    *(uint2*)&out[((long)z * N + n0 + r) * K + k0 + c] = o2;
}

// ---------------------------------------------------------------------------
// Transpose fp16 -> fp16 (for per-head V^T): in [K][N] halves -> out[(z*N+n)*K+k]
// ---------------------------------------------------------------------------
__global__ void __launch_bounds__(256)
trh(const __half* __restrict__ in, __half* __restrict__ out,
    int K, int N, int ldin, int zdiv, long sZb, long sZh)
{
    __shared__ __half t[32][36];
    const int z = blockIdx.z, zb = z / zdiv, zh = z % zdiv;
    in += zb * sZb + zh * sZh;
    const int k0 = blockIdx.x * 32, n0 = blockIdx.y * 32;
    const int r = threadIdx.x >> 3, c = (threadIdx.x & 7) * 4;

    const uint2 v = *(const uint2*)&in[(long)(k0 + r) * ldin + n0 + c];
    *(uint2*)&t[r][c] = v;
    __syncthreads();

    __half2 a, b;
    a = __halves2half2(t[c + 0][r], t[c + 1][r]);
    b = __halves2half2(t[c + 2][r], t[c + 3][r]);
    uint2 o2 = make_uint2(*(unsigned*)&a, *(unsigned*)&b);
    *(uint2*)&out[((long)z * N + n0 + r) * K + k0 + c] = o2;
}

// ---------------------------------------------------------------------------
// fp16 TC GEMM: BM=BN=128, BK=32, 256 thr (8 warps: 4M x 2N, warp tile 32x64).
// 3-stage cp.async pipeline, ldmatrix both operands, fp32 accumulate.
// A [m][k] fp16, Bt [n][k] fp16. flags: 1=bias, 2=residual, 4=relu, 16=half out
// ---------------------------------------------------------------------------
constexpr int STH   = 40;                      // halves per row (32 + 8 pad)
constexpr int ABUFB = 128 * STH * 2;           // 10240 bytes per operand stage
constexpr int GSMEM = 3 * 2 * ABUFB;           // 61440 bytes

__global__ void __launch_bounds__(256, 2)
gemm_tc(const __half* __restrict__ A, const __half* __restrict__ Bt,
        const float* __restrict__ bias, const float* __restrict__ Res,
        void* __restrict__ Cv, int K, int lda, int ldb, int ldc, int zdiv,
        long sAb, long sAh, long sBb, long sBh, long sCb, long sCh,
        int flags)
{
    extern __shared__ __half hsm[];
    __half* Asm = hsm;
    __half* Bsm = hsm + 3 * 128 * STH;

    const int zb = blockIdx.z / zdiv, zh = blockIdx.z % zdiv;
    A  += zb * sAb + zh * sAh;
    Bt += zb * sBb + zh * sBh;
    const long coff = (long)zb * sCb + (long)zh * sCh;

    const int m0 = blockIdx.x * 128;
    const int n0 = blockIdx.y * 128;
    const int tid = threadIdx.x;

    const int ar = tid >> 1, aw = (tid & 1) * 16;      // 16 halves = 32B per thread
    const __half* Ag = A + (long)(m0 + ar) * lda + aw;
    const unsigned aDst = smu32(&Asm[ar * STH + aw]);
    const __half* Bg = Bt + (long)(n0 + ar) * ldb + aw;
    const unsigned bDst = smu32(&Bsm[ar * STH + aw]);

    const int nit = K / 32;
    auto fill = [&](int s) {
        const int st = s % 3;
        const unsigned ao = aDst + st * ABUFB;
        const __half* ag = Ag + s * 32;
        cp16(ao, ag); cp16(ao + 16, ag + 8);
        const unsigned bo = bDst + st * ABUFB;
        const __half* bg = Bg + s * 32;
        cp16(bo, bg); cp16(bo + 16, bg + 8);
    };

    const int lane = tid & 31, wid = tid >> 5;
    const int wm = wid & 3, wn = wid >> 2;
    const int grp = lane >> 2, qd = lane & 3;

    const unsigned aAddr = smu32(&Asm[(wm * 32 + (lane & 15)) * STH]) + ((lane & 16) ? 16 : 0);
    const unsigned bAddr = smu32(&Bsm[(wn * 64 + (lane & 15)) * STH]) + ((lane & 16) ? 16 : 0);

    float acc[2][8][4];
    #pragma unroll
    for (int i = 0; i < 2; i++)
        #pragma unroll
        for (int j = 0; j < 8; j++)
            #pragma unroll
            for (int l = 0; l < 4; l++) acc[i][j][l] = 0.f;

    fill(0); CP_COMMIT;
    if (nit > 1) fill(1);
    CP_COMMIT;

    for (int it = 0; it < nit; it++) {
        CP_WAIT1;
        __syncthreads();
        if (it + 2 < nit) fill(it + 2);
        CP_COMMIT;

        const int st = it % 3;
        const unsigned aC = aAddr + st * ABUFB;
        const unsigned bC = bAddr + st * ABUFB;
        #pragma unroll
        for (int ks = 0; ks < 2; ks++) {
            const uint4 a0 = ldm4(aC + ks * 32);
            const uint4 a1 = ldm4(aC + 16 * STH * 2 + ks * 32);
            #pragma unroll
            for (int p = 0; p < 4; p++) {
                const uint4 bv = ldm4(bC + p * 16 * STH * 2 + ks * 32);
                mma16(acc[0][2 * p],     a0, bv.x, bv.z);
                mma16(acc[0][2 * p + 1], a0, bv.y, bv.w);
                mma16(acc[1][2 * p],     a1, bv.x, bv.z);
                mma16(acc[1][2 * p + 1], a1, bv.y, bv.w);
            }
        }
    }

    const bool dob = flags & 1, dores = flags & 2, dorelu = flags & 4,
               dohalf = flags & 16;
    #pragma unroll
    for (int mt = 0; mt < 2; mt++) {
        #pragma unroll
        for (int nt = 0; nt < 8; nt++) {
            const int r = m0 + wm * 32 + mt * 16 + grp;
            const int c = n0 + wn * 64 + nt * 8 + qd * 2;
            #pragma unroll
            for (int hf = 0; hf < 2; hf++) {
                const int rr = r + hf * 8;
                float v0 = acc[mt][nt][hf * 2 + 0];
                float v1 = acc[mt][nt][hf * 2 + 1];
                if (dob) { v0 += bias[c]; v1 += bias[c + 1]; }
                if (dores) {
                    const float* rp = Res + coff + (long)rr * ldc + c;
                    v0 += rp[0]; v1 += rp[1];
                }
                if (dorelu) { v0 = fmaxf(v0, 0.f); v1 = fmaxf(v1, 0.f); }
                if (dohalf) {
                    const unsigned h = h2pack(v0, v1);
                    *(unsigned*)((__half*)Cv + coff + (long)rr * ldc + c) = h;
                } else {
                    *(float2*)((float*)Cv + coff + (long)rr * ldc + c) = make_float2(v0, v1);
                }
            }
        }
    }
}

// ---------------------------------------------------------------------------
// Flash attention (fp16 operands, fp32 math): 128 q-rows/CTA, 64-wide j tiles.
// ---------------------------------------------------------------------------
constexpr int FSH = 72;   // halves per row (64 + 8 pad) = 144 bytes
constexpr int FA_SMEM = (128 + 64 + 64 + 128) * FSH * 2;   // 55296 B

__global__ void __launch_bounds__(256, 2)
flash_attn(const __half* __restrict__ q, const __half* __restrict__ k,
           const __half* __restrict__ vt, __half* __restrict__ o)
{
    extern __shared__ __half fsm[];
    __half* Qs  = fsm;                   // [128][FSH]
    __half* Ks  = Qs  + 128 * FSH;       // [64][FSH]
    __half* Vts = Ks  + 64 * FSH;        // [64][FSH]
    __half* Ps  = Vts + 64 * FSH;        // [128][FSH]

    const int z = blockIdx.y;
    const int b = z >> 4, h = z & 15;
    const int i0 = blockIdx.x * 128;
    const int tid = threadIdx.x, lane = tid & 31, w = tid >> 5;
    const int grp = lane >> 2, qd = lane & 3;

    {   // Q fill: 128 rows x 64 halves (128B/row)
        const int r = tid >> 1, cb = (tid & 1) * 32;
        const __half* src = q + (long)(b * NS + i0 + r) * DM + h * DH + cb;
        unsigned dst = smu32(Qs + r * FSH + cb);
        #pragma unroll
        for (int i = 0; i < 4; i++) cp16(dst + i * 16, src + i * 8);
        CP_COMMIT;
    }

    const int r0 = w * 16;
    const int gr = i0 + r0 + grp;
    const unsigned qAddr = smu32(Qs + (r0 + (lane & 15)) * FSH) + ((lane & 16) ? 16 : 0);
    const unsigned kAddr = smu32(Ks + (lane & 15) * FSH) + ((lane & 16) ? 16 : 0);
    const unsigned vAddr = smu32(Vts + (lane & 15) * FSH) + ((lane & 16) ? 16 : 0);
    const unsigned pAddr = smu32(Ps + (r0 + (lane & 15)) * FSH) + ((lane & 16) ? 16 : 0);

    float m0 = -1e30f, m1 = -1e30f, l0 = 0.f, l1 = 0.f;
    float oacc[8][4];
    #pragma unroll
    for (int i = 0; i < 8; i++)
        #pragma unroll
        for (int j = 0; j < 4; j++) oacc[i][j] = 0.f;

    const int ntiles = i0 / 64 + 2;

    for (int jt = 0; jt < ntiles; jt++) {
        const int j0 = jt * 64;
        __syncthreads();
        {   // K/V tiles: 64 rows x 64 halves each
            const int jj = tid >> 2, cb = (tid & 3) * 16;
            const __half* ks = k + (long)(b * NS + j0 + jj) * DM + h * DH + cb;
            unsigned kd = smu32(Ks + jj * FSH + cb);
            cp16(kd, ks); cp16(kd + 16, ks + 8);
            const __half* vs = vt + ((long)z * DH + jj) * NS + j0 + cb;
            unsigned vd = smu32(Vts + jj * FSH + cb);
            cp16(vd, vs); cp16(vd + 16, vs + 8);
            CP_COMMIT;
        }
        CP_WAIT0;
        __syncthreads();

        if (j0 <= i0 + r0 + 15) {
            float sacc[8][4];
            #pragma unroll
            for (int i = 0; i < 8; i++)
                #pragma unroll
                for (int j = 0; j < 4; j++) sacc[i][j] = 0.f;

            #pragma unroll
            for (int ks = 0; ks < 4; ks++) {
                const uint4 af = ldm4(qAddr + ks * 32);
                #pragma unroll
                for (int p = 0; p < 4; p++) {
                    const uint4 bv = ldm4(kAddr + p * 16 * FSH * 2 + ks * 32);
                    mma16(sacc[2 * p],     af, bv.x, bv.z);
                    mma16(sacc[2 * p + 1], af, bv.y, bv.w);
                }
            }

            float mx0 = -1e30f, mx1 = -1e30f;
            #pragma unroll
            for (int nt = 0; nt < 8; nt++) {
                const int jc = j0 + nt * 8 + qd * 2;
                float v0 = sacc[nt][0] * 0.125f, v1 = sacc[nt][1] * 0.125f;
                float v2 = sacc[nt][2] * 0.125f, v3 = sacc[nt][3] * 0.125f;
                if (jc     > gr)     v0 = -1e30f;
                if (jc + 1 > gr)     v1 = -1e30f;
                if (jc     > gr + 8) v2 = -1e30f;
                if (jc + 1 > gr + 8) v3 = -1e30f;
                sacc[nt][0] = v0; sacc[nt][1] = v1; sacc[nt][2] = v2; sacc[nt][3] = v3;
                mx0 = fmaxf(mx0, fmaxf(v0, v1));
                mx1 = fmaxf(mx1, fmaxf(v2, v3));
            }
            mx0 = fmaxf(mx0, __shfl_xor_sync(0xffffffffu, mx0, 1));
            mx0 = fmaxf(mx0, __shfl_xor_sync(0xffffffffu, mx0, 2));
            mx1 = fmaxf(mx1, __shfl_xor_sync(0xffffffffu, mx1, 1));
            mx1 = fmaxf(mx1, __shfl_xor_sync(0xffffffffu, mx1, 2));
            const float mn0 = fmaxf(m0, mx0), mn1 = fmaxf(m1, mx1);
            const float es0 = expf(m0 - mn0), es1 = expf(m1 - mn1);
            m0 = mn0; m1 = mn1;

            float rs0 = 0.f, rs1 = 0.f;
            const int lr = r0 + grp;
            #pragma unroll
            for (int nt = 0; nt < 8; nt++) {
                const float p0 = expf(sacc[nt][0] - mn0);
                const float p1 = expf(sacc[nt][1] - mn0);
                const float p2 = expf(sacc[nt][2] - mn1);
                const float p3 = expf(sacc[nt][3] - mn1);
                rs0 += p0 + p1; rs1 += p2 + p3;
                *(unsigned*)(Ps + lr * FSH + nt * 8 + qd * 2) = h2pack(p0, p1);
                *(unsigned*)(Ps + (lr + 8) * FSH + nt * 8 + qd * 2) = h2pack(p2, p3);
            }
            rs0 += __shfl_xor_sync(0xffffffffu, rs0, 1);
            rs0 += __shfl_xor_sync(0xffffffffu, rs0, 2);
            rs1 += __shfl_xor_sync(0xffffffffu, rs1, 1);
            rs1 += __shfl_xor_sync(0xffffffffu, rs1, 2);
            l0 = l0 * es0 + rs0;
            l1 = l1 * es1 + rs1;

            #pragma unroll
            for (int nt = 0; nt < 8; nt++) {
                oacc[nt][0] *= es0; oacc[nt][1] *= es0;
                oacc[nt][2] *= es1; oacc[nt][3] *= es1;
            }
            __syncwarp();

            #pragma unroll
            for (int ks = 0; ks < 4; ks++) {
                const uint4 pf = ldm4(pAddr + ks * 32);
                #pragma unroll
                for (int p = 0; p < 4; p++) {
                    const uint4 bv = ldm4(vAddr + p * 16 * FSH * 2 + ks * 32);
                    mma16(oacc[2 * p],     pf, bv.x, bv.z);
                    mma16(oacc[2 * p + 1], pf, bv.y, bv.w);
                }
            }
        }
    }

    const float inv0 = 1.f / l0, inv1 = 1.f / l1;
    #pragma unroll
    for (int nt = 0; nt < 8; nt++) {
        const int c = h * DH + nt * 8 + qd * 2;
        *(unsigned*)(o + (long)(b * NS + gr) * DM + c) =
            h2pack(oacc[nt][0] * inv0, oacc[nt][1] * inv0);
        *(unsigned*)(o + (long)(b * NS + gr + 8) * DM + c) =
            h2pack(oacc[nt][2] * inv1, oacc[nt][3] * inv1);
    }
}

// ---------------------------------------------------------------------------
__global__ void __launch_bounds__(256)
ln_kernel(const float* __restrict__ in, const float* __restrict__ g,
          const float* __restrict__ b, float* __restrict__ out,
          __half* __restrict__ outh)
{
    const float* p = in + (long)blockIdx.x * DM;
    float*  po = out  + (long)blockIdx.x * DM;
    __half* ph = outh + (long)blockIdx.x * DM;
    const int tid = threadIdx.x;
    __shared__ float red[256];
    float vals[4];
    float s = 0.f;
    #pragma unroll
    for (int i = 0; i < 4; i++) { vals[i] = p[tid + i * 256]; s += vals[i]; }
    red[tid] = s; __syncthreads();
    for (int st = 128; st > 0; st >>= 1) {
        if (tid < st) red[tid] += red[tid + st];
        __syncthreads();
    }
    const float mean = red[0] * (1.f / DM); __syncthreads();
    float sq = 0.f;
    #pragma unroll
    for (int i = 0; i < 4; i++) { float d = vals[i] - mean; sq += d * d; }
    red[tid] = sq; __syncthreads();
    for (int st = 128; st > 0; st >>= 1) {
        if (tid < st) red[tid] += red[tid + st];
        __syncthreads();
    }
    const float sd = sqrtf(red[0] / (DM - 1));
    const float inv = 1.f / (sd + 1e-6f);
    #pragma unroll
    for (int i = 0; i < 4; i++) {
        const int d = tid + i * 256;
        const float r = g[d] * (vals[i] - mean) * inv + b[d];
        po[d] = r;
        ph[d] = __float2half_rn(r);
    }
}

__global__ void __launch_bounds__(256)
embed_kernel(const int* __restrict__ tokens, const float* __restrict__ emb,
             float* __restrict__ x, __half* __restrict__ xh)
{
    const int t = blockIdx.x;
    const int s = t & (NS - 1);
    const float* e = emb + (long)tokens[t] * DM;
    float*  xo = x  + (long)t * DM;
    __half* xp = xh + (long)t * DM;
    const float nlog = -9.210340371976184f / (float)DM;
    for (int d = threadIdx.x; d < DM; d += 256) {
        const float freq = expf((float)(d & ~1) * nlog);
        const float ang = (float)s * freq;
        const float r = e[d] * 32.0f + ((d & 1) ? cosf(ang) : sinf(ang));
        xo[d] = r;
        xp[d] = __float2half_rn(r);
    }
}

// ---------------------------------------------------------------------------
extern "C" void kernel_launch(void* const* d_in, const int* in_sizes, int n_in,
                              void* d_out, int out_size)
{
    const int*   tokens = (const int*)  d_in[0];
    const float* emb    = (const float*)d_in[1];
    const float* Wq     = (const float*)d_in[2];
    const float* Wk     = (const float*)d_in[3];
    const float* Wv     = (const float*)d_in[4];
    const float* Wo     = (const float*)d_in[5];
    const float* bo     = (const float*)d_in[6];
    const float* ln1g   = (const float*)d_in[7];
    const float* ln1b   = (const float*)d_in[8];
    const float* W1     = (const float*)d_in[9];
    const float* b1     = (const float*)d_in[10];
    const float* W2     = (const float*)d_in[11];
    const float* b2     = (const float*)d_in[12];
    const float* ln2g   = (const float*)d_in[13];
    const float* ln2b   = (const float*)d_in[14];
    const float* Wout   = (const float*)d_in[15];
    const float* bout   = (const float*)d_in[16];
    float* out = (float*)d_out;

    float *x, *res;
    __half *xh, *qkv, *o, *ffn, *vt, *bt;
    cudaGetSymbolAddress((void**)&x,   g_x);
    cudaGetSymbolAddress((void**)&xh,  g_xh);
    cudaGetSymbolAddress((void**)&res, g_res);
    cudaGetSymbolAddress((void**)&qkv, g_qkv);
    cudaGetSymbolAddress((void**)&o,   g_o);
    cudaGetSymbolAddress((void**)&ffn, g_ffn);
    cudaGetSymbolAddress((void**)&vt,  g_vt);
    cudaGetSymbolAddress((void**)&bt,  g_bt);

    cudaFuncSetAttribute(gemm_tc,    cudaFuncAttributeMaxDynamicSharedMemorySize, GSMEM);
    cudaFuncSetAttribute(flash_attn, cudaFuncAttributeMaxDynamicSharedMemorySize, FA_SMEM);

    __half* q = qkv;
    __half* k = qkv + NT * DM;
    __half* v = qkv + 2 * NT * DM;
    const long HW = (long)NH * DM * DH;

    embed_kernel<<<NT, 256>>>(tokens, emb, x, xh);

    for (int l = 0; l < NL; l++) {
        // QKV weights -> bt[(h*64+n)*DM + k] (fp16), fused z=3 GEMM
        tr16<<<dim3(DM / 32, DH / 32, NH), 256>>>(Wq + l * HW, bt,          DM, DH, DH, NH, 0, (long)DM * DH);
        tr16<<<dim3(DM / 32, DH / 32, NH), 256>>>(Wk + l * HW, bt + HW,     DM, DH, DH, NH, 0, (long)DM * DH);
        tr16<<<dim3(DM / 32, DH / 32, NH), 256>>>(Wv + l * HW, bt + 2 * HW, DM, DH, DH, NH, 0, (long)DM * DH);
        gemm_tc<<<dim3(NT / 128, DM / 128, 3), 256, GSMEM>>>(
            xh, bt, nullptr, nullptr, qkv, DM, DM, DM, DM, 3,
            0, 0, 0, HW, 0, (long)NT * DM, 16);

        // V^T per head (fp16)
        trh<<<dim3(NS / 32, DH / 32, NB * NH), 256>>>(
            v, vt, NS, DH, DM, NH, (long)NS * DM, DH);

        // flash attention -> o (fp16)
        flash_attn<<<dim3(NS / 128, NB * NH), 256, FA_SMEM>>>(q, k, vt, o);

        // O projection + bias + residual (fp32 out)
        tr16<<<dim3(DM / 32, DM / 32, 1), 256>>>(Wo + (long)l * DM * DM, bt, DM, DM, DM, 1, 0, 0);
        gemm_tc<<<dim3(NT / 128, DM / 128), 256, GSMEM>>>(
            o, bt, bo + l * DM, x, res, DM, DM, DM, DM, 1,
            0, 0, 0, 0, 0, 0, 1 | 2);
        ln_kernel<<<NT, 256>>>(res, ln1g + l * DM, ln1b + l * DM, x, xh);

        // FFN
        tr16<<<dim3(DM / 32, DFF / 32, 1), 256>>>(W1 + (long)l * DM * DFF, bt, DM, DFF, DFF, 1, 0, 0);
        gemm_tc<<<dim3(NT / 128, DFF / 128), 256, GSMEM>>>(
            xh, bt, b1 + l * DFF, nullptr, ffn, DM, DM, DM, DFF, 1,
            0, 0, 0, 0, 0, 0, 1 | 4 | 16);
        tr16<<<dim3(DFF / 32, DM / 32, 1), 256>>>(W2 + (long)l * DFF * DM, bt, DFF, DM, DM, 1, 0, 0);
        gemm_tc<<<dim3(NT / 128, DM / 128), 256, GSMEM>>>(
            ffn, bt, b2 + l * DM, x, res, DFF, DFF, DFF, DM, 1,
            0, 0, 0, 0, 0, 0, 1 | 2);
        ln_kernel<<<NT, 256>>>(res, ln2g + l * DM, ln2b + l * DM, x, xh);
    }

    // final vocab projection (fp32 out)
    tr16<<<dim3(DM / 32, NV / 32, 1), 256>>>(Wout, bt, DM, NV, NV, 1, 0, 0);
    gemm_tc<<<dim3(NT / 128, NV / 128), 256, GSMEM>>>(
        xh, bt, bout, nullptr, out, DM, DM, DM, NV, 1,
        0, 0, 0, 0, 0, 0, 1);
}

// round 14
// speedup vs baseline: 3.2331x; 1.1188x over previous
#include <cuda_runtime.h>
#include <cuda_fp16.h>
#include <cstdint>

constexpr int NL  = 6;
constexpr int NH  = 16;
constexpr int DM  = 1024;
constexpr int DH  = 64;
constexpr int DFF = 4096;
constexpr int NV  = 32000;
constexpr int NB  = 2;
constexpr int NS  = 1024;
constexpr int NT  = NB * NS;

__device__ float  g_x  [NT * DM];                 // fp32 residual path
__device__ __half g_xh [NT * DM];                 // fp16 copy
__device__ float  g_res[NT * DM];
__device__ __half g_qkv[3 * NT * DM];             // fp16 q,k,v
__device__ __half g_o  [NT * DM];                 // fp16 attn out
__device__ __half g_ffn[NT * DFF];                // fp16
__device__ __half g_bt [(long)NV * DM];           // fp16 converted weights (native layout)

__device__ __forceinline__ void mma16(float* c, const uint4& a, unsigned b0, unsigned b1) {
    asm volatile(
        "mma.sync.aligned.m16n8k16.row.col.f32.f16.f16.f32 "
        "{%0,%1,%2,%3}, {%4,%5,%6,%7}, {%8,%9}, {%0,%1,%2,%3};"
        : "+f"(c[0]), "+f"(c[1]), "+f"(c[2]), "+f"(c[3])
        : "r"(a.x), "r"(a.y), "r"(a.z), "r"(a.w), "r"(b0), "r"(b1));
}
__device__ __forceinline__ uint4 ldm4(unsigned addr) {
    uint4 r;
    asm volatile("ldmatrix.sync.aligned.m8n8.x4.shared.b16 {%0,%1,%2,%3}, [%4];"
                 : "=r"(r.x), "=r"(r.y), "=r"(r.z), "=r"(r.w) : "r"(addr));
    return r;
}
__device__ __forceinline__ uint4 ldm4t(unsigned addr) {
    uint4 r;
    asm volatile("ldmatrix.sync.aligned.m8n8.x4.trans.shared.b16 {%0,%1,%2,%3}, [%4];"
                 : "=r"(r.x), "=r"(r.y), "=r"(r.z), "=r"(r.w) : "r"(addr));
    return r;
}
__device__ __forceinline__ void cp16(unsigned sm, const void* g) {
    asm volatile("cp.async.ca.shared.global [%0], [%1], 16;" :: "r"(sm), "l"(g));
}
#define CP_COMMIT asm volatile("cp.async.commit_group;" ::: "memory")
#define CP_WAIT1  asm volatile("cp.async.wait_group 1;" ::: "memory")
#define CP_WAIT0  asm volatile("cp.async.wait_group 0;" ::: "memory")

__device__ __forceinline__ unsigned smu32(const void* p) {
    return (unsigned)__cvta_generic_to_shared(p);
}
__device__ __forceinline__ unsigned h2pack(float a, float b) {
    const __half2 h = __floats2half2_rn(a, b);
    return *(const unsigned*)&h;
}

// ---------------------------------------------------------------------------
// Pure fp32 -> fp16 convert (layout-preserving), 8 elems/thread.
// ---------------------------------------------------------------------------
__global__ void __launch_bounds__(256)
cvt16(const float* __restrict__ in, __half* __restrict__ out)
{
    const long i = ((long)blockIdx.x * 256 + threadIdx.x) * 8;
    const float4 a = *(const float4*)(in + i);
    const float4 b = *(const float4*)(in + i + 4);
    uint4 o;
    o.x = h2pack(a.x, a.y);
    o.y = h2pack(a.z, a.w);
    o.z = h2pack(b.x, b.y);
    o.w = h2pack(b.z, b.w);
    *(uint4*)(out + i) = o;
}

// ---------------------------------------------------------------------------
// fp16 TC GEMM: BM=BN=128, BK=32, 256 thr (8 warps: 4M x 2N, warp tile 32x64).
// A [m][k] fp16 (ldmatrix). B NATIVE [k][n] fp16 (ldmatrix.trans):
//   element (k, n) at Bt + (n>>nshift)*sHead + k*ldb + (n & ((1<<nshift)-1)).
// 3-stage cp.async pipeline, fp32 accumulate.
// flags: 1=bias, 2=residual, 4=relu, 16=half out
// ---------------------------------------------------------------------------
constexpr int STH   = 40;                      // A row: 32 + 8 pad halves
constexpr int BST   = 136;                     // B row: 128 + 8 pad halves
constexpr int ABUFB = 128 * STH * 2;           // 10240 B
constexpr int BBUFB = 32 * BST * 2;            // 8704 B
constexpr int GSMEM = 3 * (ABUFB + BBUFB);     // 56832 B

__global__ void __launch_bounds__(256, 2)
gemm_tc(const __half* __restrict__ A, const __half* __restrict__ Bt,
        const float* __restrict__ bias, const float* __restrict__ Res,
        void* __restrict__ Cv, int K, int lda, int ldb, int ldc, int zdiv,
        long sAb, long sAh, long sBh, long sCb, long sCh,
        int nshift, long sHead, int flags)
{
    extern __shared__ __half hsm[];
    __half* Asm = hsm;
    __half* Bsm = hsm + 3 * 128 * STH;

    const int zb = blockIdx.z / zdiv, zh = blockIdx.z % zdiv;
    A  += zb * sAb + zh * sAh;
    Bt += zh * sBh;
    const long coff = (long)zb * sCb + (long)zh * sCh;

    const int m0 = blockIdx.x * 128;
    const int n0 = blockIdx.y * 128;
    const int tid = threadIdx.x;

    // A fill: 128 rows x 32 halves, thread -> 16 halves (2 cp16)
    const int ar = tid >> 1, aw = (tid & 1) * 16;
    const __half* Ag = A + (long)(m0 + ar) * lda + aw;
    const unsigned aDst = smu32(&Asm[ar * STH + aw]);
    // B fill: 32 k-rows x 128 halves; thread -> row tid>>3, two 8-half chunks
    const int br = tid >> 3, bc = (tid & 7) * 8;
    const int gn0 = n0 + bc, gn1 = gn0 + 64;
    const unsigned nmask = (1u << nshift) - 1u;
    const __half* Bg0 = Bt + (long)(gn0 >> nshift) * sHead + (gn0 & nmask);
    const __half* Bg1 = Bt + (long)(gn1 >> nshift) * sHead + (gn1 & nmask);
    const unsigned bDst = smu32(&Bsm[br * BST + bc]);

    const int nit = K / 32;
    auto fill = [&](int s) {
        const int st = s % 3;
        const unsigned ao = aDst + st * ABUFB;
        const __half* ag = Ag + s * 32;
        cp16(ao, ag); cp16(ao + 16, ag + 8);
        const unsigned bo = bDst + st * BBUFB;
        const long krow = (long)(s * 32 + br) * ldb;
        cp16(bo, Bg0 + krow);
        cp16(bo + 128, Bg1 + krow);
    };

    const int lane = tid & 31, wid = tid >> 5;
    const int wm = wid & 3, wn = wid >> 2;
    const int grp = lane >> 2, qd = lane & 3;

    const unsigned aAddr = smu32(&Asm[(wm * 32 + (lane & 15)) * STH]) + ((lane & 16) ? 16 : 0);
    const unsigned bAddr = smu32(&Bsm[(lane & 15) * BST + wn * 64]) + ((lane & 16) ? 16 : 0);

    float acc[2][8][4];
    #pragma unroll
    for (int i = 0; i < 2; i++)
        #pragma unroll
        for (int j = 0; j < 8; j++)
            #pragma unroll
            for (int l = 0; l < 4; l++) acc[i][j][l] = 0.f;

    fill(0); CP_COMMIT;
    if (nit > 1) fill(1);
    CP_COMMIT;

    for (int it = 0; it < nit; it++) {
        CP_WAIT1;
        __syncthreads();
        if (it + 2 < nit) fill(it + 2);
        CP_COMMIT;

        const int st = it % 3;
        const unsigned aC = aAddr + st * ABUFB;
        const unsigned bC = bAddr + st * BBUFB;
        #pragma unroll
        for (int ks = 0; ks < 2; ks++) {
            const uint4 a0 = ldm4(aC + ks * 32);
            const uint4 a1 = ldm4(aC + 16 * STH * 2 + ks * 32);
            #pragma unroll
            for (int p = 0; p < 4; p++) {
                const uint4 bv = ldm4t(bC + ks * 16 * BST * 2 + p * 32);
                mma16(acc[0][2 * p],     a0, bv.x, bv.y);
                mma16(acc[0][2 * p + 1], a0, bv.z, bv.w);
                mma16(acc[1][2 * p],     a1, bv.x, bv.y);
                mma16(acc[1][2 * p + 1], a1, bv.z, bv.w);
            }
        }
    }

    const bool dob = flags & 1, dores = flags & 2, dorelu = flags & 4,
               dohalf = flags & 16;
    #pragma unroll
    for (int mt = 0; mt < 2; mt++) {
        #pragma unroll
        for (int nt = 0; nt < 8; nt++) {
            const int r = m0 + wm * 32 + mt * 16 + grp;
            const int c = n0 + wn * 64 + nt * 8 + qd * 2;
            #pragma unroll
            for (int hf = 0; hf < 2; hf++) {
                const int rr = r + hf * 8;
                float v0 = acc[mt][nt][hf * 2 + 0];
                float v1 = acc[mt][nt][hf * 2 + 1];
                if (dob) { v0 += bias[c]; v1 += bias[c + 1]; }
                if (dores) {
                    const float* rp = Res + coff + (long)rr * ldc + c;
                    v0 += rp[0]; v1 += rp[1];
                }
                if (dorelu) { v0 = fmaxf(v0, 0.f); v1 = fmaxf(v1, 0.f); }
                if (dohalf) {
                    *(unsigned*)((__half*)Cv + coff + (long)rr * ldc + c) = h2pack(v0, v1);
                } else {
                    *(float2*)((float*)Cv + coff + (long)rr * ldc + c) = make_float2(v0, v1);
                }
            }
        }
    }
}

// ---------------------------------------------------------------------------
// Flash attention (fp16 operands, fp32 math): 128 q-rows/CTA, 64-wide j tiles.
// V consumed natively [j][c] via ldmatrix.trans (no V^T buffer).
// ---------------------------------------------------------------------------
constexpr int FSH = 72;   // halves per row (64 + 8 pad)
constexpr int FA_SMEM = (128 + 64 + 64 + 128) * FSH * 2;   // 55296 B

__global__ void __launch_bounds__(256, 2)
flash_attn(const __half* __restrict__ q, const __half* __restrict__ k,
           const __half* __restrict__ v, __half* __restrict__ o)
{
    extern __shared__ __half fsm[];
    __half* Qs = fsm;                   // [128][FSH]
    __half* Ks = Qs + 128 * FSH;        // [64][FSH]  rows j, cols c
    __half* Vs = Ks + 64 * FSH;         // [64][FSH]  rows j, cols c (native)
    __half* Ps = Vs + 64 * FSH;         // [128][FSH] rows q, cols j

    const int z = blockIdx.y;
    const int b = z >> 4, h = z & 15;
    const int i0 = blockIdx.x * 128;
    const int tid = threadIdx.x, lane = tid & 31, w = tid >> 5;
    const int grp = lane >> 2, qd = lane & 3;

    {   // Q fill: 128 rows x 64 halves
        const int r = tid >> 1, cb = (tid & 1) * 32;
        const __half* src = q + (long)(b * NS + i0 + r) * DM + h * DH + cb;
        unsigned dst = smu32(Qs + r * FSH + cb);
        #pragma unroll
        for (int i = 0; i < 4; i++) cp16(dst + i * 16, src + i * 8);
        CP_COMMIT;
    }

    const int r0 = w * 16;
    const int gr = i0 + r0 + grp;
    const unsigned qAddr = smu32(Qs + (r0 + (lane & 15)) * FSH) + ((lane & 16) ? 16 : 0);
    const unsigned kAddr = smu32(Ks + (lane & 15) * FSH) + ((lane & 16) ? 16 : 0);
    const unsigned vAddr = smu32(Vs + (lane & 15) * FSH) + ((lane & 16) ? 16 : 0);
    const unsigned pAddr = smu32(Ps + (r0 + (lane & 15)) * FSH) + ((lane & 16) ? 16 : 0);

    float m0 = -1e30f, m1 = -1e30f, l0 = 0.f, l1 = 0.f;
    float oacc[8][4];
    #pragma unroll
    for (int i = 0; i < 8; i++)
        #pragma unroll
        for (int j = 0; j < 4; j++) oacc[i][j] = 0.f;

    const int ntiles = i0 / 64 + 2;

    for (int jt = 0; jt < ntiles; jt++) {
        const int j0 = jt * 64;
        __syncthreads();
        {   // K and V tiles: 64 rows x 64 halves each, identical addressing
            const int jj = tid >> 2, cb = (tid & 3) * 16;
            const long row = (long)(b * NS + j0 + jj) * DM + h * DH + cb;
            const __half* ks = k + row;
            unsigned kd = smu32(Ks + jj * FSH + cb);
            cp16(kd, ks); cp16(kd + 16, ks + 8);
            const __half* vs = v + row;
            unsigned vd = smu32(Vs + jj * FSH + cb);
            cp16(vd, vs); cp16(vd + 16, vs + 8);
            CP_COMMIT;
        }
        CP_WAIT0;
        __syncthreads();

        if (j0 <= i0 + r0 + 15) {
            float sacc[8][4];
            #pragma unroll
            for (int i = 0; i < 8; i++)
                #pragma unroll
                for (int j = 0; j < 4; j++) sacc[i][j] = 0.f;

            #pragma unroll
            for (int ks = 0; ks < 4; ks++) {
                const uint4 af = ldm4(qAddr + ks * 32);
                #pragma unroll
                for (int p = 0; p < 4; p++) {
                    const uint4 bv = ldm4(kAddr + p * 16 * FSH * 2 + ks * 32);
                    mma16(sacc[2 * p],     af, bv.x, bv.z);
                    mma16(sacc[2 * p + 1], af, bv.y, bv.w);
                }
            }

            float mx0 = -1e30f, mx1 = -1e30f;
            #pragma unroll
            for (int nt = 0; nt < 8; nt++) {
                const int jc = j0 + nt * 8 + qd * 2;
                float v0 = sacc[nt][0] * 0.125f, v1 = sacc[nt][1] * 0.125f;
                float v2 = sacc[nt][2] * 0.125f, v3 = sacc[nt][3] * 0.125f;
                if (jc     > gr)     v0 = -1e30f;
                if (jc + 1 > gr)     v1 = -1e30f;
                if (jc     > gr + 8) v2 = -1e30f;
                if (jc + 1 > gr + 8) v3 = -1e30f;
                sacc[nt][0] = v0; sacc[nt][1] = v1; sacc[nt][2] = v2; sacc[nt][3] = v3;
                mx0 = fmaxf(mx0, fmaxf(v0, v1));
                mx1 = fmaxf(mx1, fmaxf(v2, v3));
            }
            mx0 = fmaxf(mx0, __shfl_xor_sync(0xffffffffu, mx0, 1));
            mx0 = fmaxf(mx0, __shfl_xor_sync(0xffffffffu, mx0, 2));
            mx1 = fmaxf(mx1, __shfl_xor_sync(0xffffffffu, mx1, 1));
            mx1 = fmaxf(mx1, __shfl_xor_sync(0xffffffffu, mx1, 2));
            const float mn0 = fmaxf(m0, mx0), mn1 = fmaxf(m1, mx1);
            const float es0 = expf(m0 - mn0), es1 = expf(m1 - mn1);
            m0 = mn0; m1 = mn1;

            float rs0 = 0.f, rs1 = 0.f;
            const int lr = r0 + grp;
            #pragma unroll
            for (int nt = 0; nt < 8; nt++) {
                const float p0 = expf(sacc[nt][0] - mn0);
                const float p1 = expf(sacc[nt][1] - mn0);
                const float p2 = expf(sacc[nt][2] - mn1);
                const float p3 = expf(sacc[nt][3] - mn1);
                rs0 += p0 + p1; rs1 += p2 + p3;
                *(unsigned*)(Ps + lr * FSH + nt * 8 + qd * 2) = h2pack(p0, p1);
                *(unsigned*)(Ps + (lr + 8) * FSH + nt * 8 + qd * 2) = h2pack(p2, p3);
            }
            rs0 += __shfl_xor_sync(0xffffffffu, rs0, 1);
            rs0 += __shfl_xor_sync(0xffffffffu, rs0, 2);
            rs1 += __shfl_xor_sync(0xffffffffu, rs1, 1);
            rs1 += __shfl_xor_sync(0xffffffffu, rs1, 2);
            l0 = l0 * es0 + rs0;
            l1 = l1 * es1 + rs1;

            #pragma unroll
            for (int nt = 0; nt < 8; nt++) {
                oacc[nt][0] *= es0; oacc[nt][1] *= es0;
                oacc[nt][2] *= es1; oacc[nt][3] *= es1;
            }
            __syncwarp();

            // O += P @ V : P [q][j] normal, V [j][c] via trans
            #pragma unroll
            for (int ks = 0; ks < 4; ks++) {
                const uint4 pf = ldm4(pAddr + ks * 32);
                #pragma unroll
                for (int p = 0; p < 4; p++) {
                    const uint4 bv = ldm4t(vAddr + ks * 16 * FSH * 2 + p * 32);
                    mma16(oacc[2 * p],     pf, bv.x, bv.y);
                    mma16(oacc[2 * p + 1], pf, bv.z, bv.w);
                }
            }
        }
    }

    const float inv0 = 1.f / l0, inv1 = 1.f / l1;
    #pragma unroll
    for (int nt = 0; nt < 8; nt++) {
        const int c = h * DH + nt * 8 + qd * 2;
        *(unsigned*)(o + (long)(b * NS + gr) * DM + c) =
            h2pack(oacc[nt][0] * inv0, oacc[nt][1] * inv0);
        *(unsigned*)(o + (long)(b * NS + gr + 8) * DM + c) =
            h2pack(oacc[nt][2] * inv1, oacc[nt][3] * inv1);
    }
}

// ---------------------------------------------------------------------------
__global__ void __launch_bounds__(256)
ln_kernel(const float* __restrict__ in, const float* __restrict__ g,
          const float* __restrict__ b, float* __restrict__ out,
          __half* __restrict__ outh)
{
    const float* p = in + (long)blockIdx.x * DM;
    float*  po = out  + (long)blockIdx.x * DM;
    __half* ph = outh + (long)blockIdx.x * DM;
    const int tid = threadIdx.x;
    __shared__ float red[256];
    float vals[4];
    float s = 0.f;
    #pragma unroll
    for (int i = 0; i < 4; i++) { vals[i] = p[tid + i * 256]; s += vals[i]; }
    red[tid] = s; __syncthreads();
    for (int st = 128; st > 0; st >>= 1) {
        if (tid < st) red[tid] += red[tid + st];
        __syncthreads();
    }
    const float mean = red[0] * (1.f / DM); __syncthreads();
    float sq = 0.f;
    #pragma unroll
    for (int i = 0; i < 4; i++) { float d = vals[i] - mean; sq += d * d; }
    red[tid] = sq; __syncthreads();
    for (int st = 128; st > 0; st >>= 1) {
        if (tid < st) red[tid] += red[tid + st];
        __syncthreads();
    }
    const float sd = sqrtf(red[0] / (DM - 1));
    const float inv = 1.f / (sd + 1e-6f);
    #pragma unroll
    for (int i = 0; i < 4; i++) {
        const int d = tid + i * 256;
        const float r = g[d] * (vals[i] - mean) * inv + b[d];
        po[d] = r;
        ph[d] = __float2half_rn(r);
    }
}

__global__ void __launch_bounds__(256)
embed_kernel(const int* __restrict__ tokens, const float* __restrict__ emb,
             float* __restrict__ x, __half* __restrict__ xh)
{
    const int t = blockIdx.x;
    const int s = t & (NS - 1);
    const float* e = emb + (long)tokens[t] * DM;
    float*  xo = x  + (long)t * DM;
    __half* xp = xh + (long)t * DM;
    const float nlog = -9.210340371976184f / (float)DM;
    for (int d = threadIdx.x; d < DM; d += 256) {
        const float freq = expf((float)(d & ~1) * nlog);
        const float ang = (float)s * freq;
        const float r = e[d] * 32.0f + ((d & 1) ? cosf(ang) : sinf(ang));
        xo[d] = r;
        xp[d] = __float2half_rn(r);
    }
}

// ---------------------------------------------------------------------------
extern "C" void kernel_launch(void* const* d_in, const int* in_sizes, int n_in,
                              void* d_out, int out_size)
{
    const int*   tokens = (const int*)  d_in[0];
    const float* emb    = (const float*)d_in[1];
    const float* Wq     = (const float*)d_in[2];
    const float* Wk     = (const float*)d_in[3];
    const float* Wv     = (const float*)d_in[4];
    const float* Wo     = (const float*)d_in[5];
    const float* bo     = (const float*)d_in[6];
    const float* ln1g   = (const float*)d_in[7];
    const float* ln1b   = (const float*)d_in[8];
    const float* W1     = (const float*)d_in[9];
    const float* b1     = (const float*)d_in[10];
    const float* W2     = (const float*)d_in[11];
    const float* b2     = (const float*)d_in[12];
    const float* ln2g   = (const float*)d_in[13];
    const float* ln2b   = (const float*)d_in[14];
    const float* Wout   = (const float*)d_in[15];
    const float* bout   = (const float*)d_in[16];
    float* out = (float*)d_out;

    float *x, *res;
    __half *xh, *qkv, *o, *ffn, *bt;
    cudaGetSymbolAddress((void**)&x,   g_x);
    cudaGetSymbolAddress((void**)&xh,  g_xh);
    cudaGetSymbolAddress((void**)&res, g_res);
    cudaGetSymbolAddress((void**)&qkv, g_qkv);
    cudaGetSymbolAddress((void**)&o,   g_o);
    cudaGetSymbolAddress((void**)&ffn, g_ffn);
    cudaGetSymbolAddress((void**)&bt,  g_bt);

    cudaFuncSetAttribute(gemm_tc,    cudaFuncAttributeMaxDynamicSharedMemorySize, GSMEM);
    cudaFuncSetAttribute(flash_attn, cudaFuncAttributeMaxDynamicSharedMemorySize, FA_SMEM);

    __half* q = qkv;
    __half* k = qkv + NT * DM;
    __half* v = qkv + 2 * NT * DM;
    const long HW = (long)NH * DM * DH;       // 1M elems per QKV weight

    embed_kernel<<<NT, 256>>>(tokens, emb, x, xh);

    for (int l = 0; l < NL; l++) {
        // convert weights fp32->fp16 (layout-preserving)
        cvt16<<<HW / 2048, 256>>>(Wq + l * HW, bt);
        cvt16<<<HW / 2048, 256>>>(Wk + l * HW, bt + HW);
        cvt16<<<HW / 2048, 256>>>(Wv + l * HW, bt + 2 * HW);
        // fused QKV GEMM: B native [h][k][dh], head = n>>6
        gemm_tc<<<dim3(NT / 128, DM / 128, 3), 256, GSMEM>>>(
            xh, bt, nullptr, nullptr, qkv, DM, DM, DH, DM, 3,
            0, 0, HW, 0, (long)NT * DM, 6, (long)DM * DH, 16);

        // flash attention -> o (fp16), V consumed natively
        flash_attn<<<dim3(NS / 128, NB * NH), 256, FA_SMEM>>>(q, k, v, o);

        // O projection + bias + residual (fp32 out); Wo native [k][n], ldb=DM
        cvt16<<<(DM * DM) / 2048, 256>>>(Wo + (long)l * DM * DM, bt);
        gemm_tc<<<dim3(NT / 128, DM / 128), 256, GSMEM>>>(
            o, bt, bo + l * DM, x, res, DM, DM, DM, DM, 1,
            0, 0, 0, 0, 0, 30, 0, 1 | 2);
        ln_kernel<<<NT, 256>>>(res, ln1g + l * DM, ln1b + l * DM, x, xh);

        // FFN
        cvt16<<<(DM * DFF) / 2048, 256>>>(W1 + (long)l * DM * DFF, bt);
        gemm_tc<<<dim3(NT / 128, DFF / 128), 256, GSMEM>>>(
            xh, bt, b1 + l * DFF, nullptr, ffn, DM, DM, DFF, DFF, 1,
            0, 0, 0, 0, 0, 30, 0, 1 | 4 | 16);
        cvt16<<<(DFF * DM) / 2048, 256>>>(W2 + (long)l * DFF * DM, bt);
        gemm_tc<<<dim3(NT / 128, DM / 128), 256, GSMEM>>>(
            ffn, bt, b2 + l * DM, x, res, DFF, DFF, DM, DM, 1,
            0, 0, 0, 0, 0, 30, 0, 1 | 2);
        ln_kernel<<<NT, 256>>>(res, ln2g + l * DM, ln2b + l * DM, x, xh);
    }

    // final vocab projection (fp32 out); Wout native [k][n], ldb=NV
    cvt16<<<((long)DM * NV) / 2048, 256>>>(Wout, bt);
    gemm_tc<<<dim3(NT / 128, NV / 128), 256, GSMEM>>>(
        xh, bt, bout, nullptr, out, DM, DM, NV, NV, 1,
        0, 0, 0, 0, 0, 30, 0, 1);
}